// round 1
// baseline (speedup 1.0000x reference)
#include <cuda_runtime.h>
#include <cfloat>

#define N_NODES 50000
#define N_EDGES 800000
#define D 128
#define BN_EPS 1e-5f

// ---------------- scratch (__device__ globals: no allocation allowed) ----------
__device__ int   g_counts[N_NODES];
__device__ int   g_rowptr[N_NODES + 1];
__device__ int   g_cursor[N_NODES];
__device__ int   g_esrc[N_EDGES];
__device__ float g_h [(size_t)N_NODES * D];   // feats + max-agg
__device__ float g_y1[(size_t)N_NODES * D];   // h@W1 + b1
__device__ float g_y2[(size_t)N_NODES * D];   // relu(bn1(y1))@W2 + b2
__device__ float g_t [(size_t)N_NODES * D];   // relu(bn2(y2))
__device__ float g_sum[3][D];
__device__ float g_ssq[3][D];
__device__ float g_mean[3][D];
__device__ float g_rstd[3][D];

// ---------------- init -------------------------------------------------------
__global__ void k_zero() {
    int i = blockIdx.x * blockDim.x + threadIdx.x;
    if (i < N_NODES) g_counts[i] = 0;
    if (i < 3 * D) {
        reinterpret_cast<float*>(g_sum)[i] = 0.f;
        reinterpret_cast<float*>(g_ssq)[i] = 0.f;
    }
}

// ---------------- CSR build: count -> scan -> scatter ------------------------
__global__ void k_count(const int* __restrict__ dst) {
    int e = blockIdx.x * blockDim.x + threadIdx.x;
    if (e < N_EDGES) atomicAdd(&g_counts[dst[e]], 1);
}

__global__ void k_scan() {  // single block, 1024 threads, tiled Hillis-Steele
    __shared__ int s[1024];
    __shared__ int carry_s;
    const int tid = threadIdx.x;
    if (tid == 0) { carry_s = 0; g_rowptr[0] = 0; }
    __syncthreads();
    for (int base = 0; base < N_NODES; base += 1024) {
        int i = base + tid;
        int v = (i < N_NODES) ? g_counts[i] : 0;
        s[tid] = v;
        __syncthreads();
        #pragma unroll
        for (int off = 1; off < 1024; off <<= 1) {
            int t = (tid >= off) ? s[tid - off] : 0;
            __syncthreads();
            s[tid] += t;
            __syncthreads();
        }
        int carry = carry_s;
        if (i < N_NODES) {
            int incl = carry + s[tid];
            g_rowptr[i + 1] = incl;
            g_cursor[i] = incl - v;  // exclusive prefix = segment start
        }
        __syncthreads();
        if (tid == 1023) carry_s = carry + s[1023];
        __syncthreads();
    }
}

__global__ void k_scatter(const int* __restrict__ src, const int* __restrict__ dst) {
    int e = blockIdx.x * blockDim.x + threadIdx.x;
    if (e < N_EDGES) {
        int p = atomicAdd(&g_cursor[dst[e]], 1);
        g_esrc[p] = src[e];
    }
}

// ---------------- max-aggregation + residual: warp per node, no atomics -------
__global__ void k_agg(const float* __restrict__ feats) {
    int w = (blockIdx.x * blockDim.x + threadIdx.x) >> 5;
    int lane = threadIdx.x & 31;
    if (w >= N_NODES) return;
    int beg = g_rowptr[w];
    int end = g_rowptr[w + 1];
    float4 acc = make_float4(-FLT_MAX, -FLT_MAX, -FLT_MAX, -FLT_MAX);
    for (int e = beg; e < end; ++e) {
        int s = g_esrc[e];
        float4 v = reinterpret_cast<const float4*>(feats + (size_t)s * D)[lane];
        acc.x = fmaxf(acc.x, v.x);
        acc.y = fmaxf(acc.y, v.y);
        acc.z = fmaxf(acc.z, v.z);
        acc.w = fmaxf(acc.w, v.w);
    }
    if (beg == end) acc = make_float4(0.f, 0.f, 0.f, 0.f);  // no in-edges -> 0
    float4 f = reinterpret_cast<const float4*>(feats + (size_t)w * D)[lane];
    float4 h = make_float4(f.x + acc.x, f.y + acc.y, f.z + acc.z, f.w + acc.w);
    reinterpret_cast<float4*>(g_h + (size_t)w * D)[lane] = h;
}

// ---------------- SGEMM 50000x128x128, fused bias + BN-stats epilogue --------
// MODE 0: A = g_h (plain),               Y = g_y1, stats -> set SOUT
// MODE 1: A = relu(bn[SIN](g_y1)) on load, Y = g_y2, stats -> set SOUT
template<int MODE, int SIN, int SOUT>
__global__ __launch_bounds__(256) void k_gemm(
    const float* __restrict__ W, const float* __restrict__ bias,
    const float* __restrict__ gam, const float* __restrict__ bet)
{
    __shared__ float As[16][128];
    __shared__ float Ws[16][128];
    const float* __restrict__ A = (MODE == 0) ? g_h : g_y1;
    float* __restrict__ Y = (MODE == 0) ? g_y1 : g_y2;

    const int tid = threadIdx.x;
    const int tx = tid & 15;
    const int ty = tid >> 4;
    const int rowBase = blockIdx.x * 128;

    float acc[8][8];
    #pragma unroll
    for (int i = 0; i < 8; ++i)
        #pragma unroll
        for (int j = 0; j < 8; ++j) acc[i][j] = 0.f;

    for (int k0 = 0; k0 < D; k0 += 16) {
        // A tile: 128 rows x 16 k, transposed into As[k][row]
        #pragma unroll
        for (int it = 0; it < 2; ++it) {
            int idx = tid + it * 256;          // 0..511 float4 slots
            int r = idx >> 2;                  // row 0..127
            int kq = (idx & 3) << 2;           // 0,4,8,12
            int grow = rowBase + r;
            float4 v = make_float4(0.f, 0.f, 0.f, 0.f);
            if (grow < N_NODES)
                v = *reinterpret_cast<const float4*>(A + (size_t)grow * D + k0 + kq);
            if (MODE == 1) {
                float vv[4] = {v.x, v.y, v.z, v.w};
                #pragma unroll
                for (int q = 0; q < 4; ++q) {
                    int kk = k0 + kq + q;
                    float t = (vv[q] - g_mean[SIN][kk]) * g_rstd[SIN][kk];
                    vv[q] = fmaxf(fmaf(gam[kk], t, bet[kk]), 0.f);
                }
                v = make_float4(vv[0], vv[1], vv[2], vv[3]);
            }
            As[kq + 0][r] = v.x;
            As[kq + 1][r] = v.y;
            As[kq + 2][r] = v.z;
            As[kq + 3][r] = v.w;
        }
        // W tile: 16 k-rows x 128 cols
        #pragma unroll
        for (int it = 0; it < 2; ++it) {
            int idx = tid + it * 256;
            int kk = idx >> 5;
            int c = (idx & 31) << 2;
            *reinterpret_cast<float4*>(&Ws[kk][c]) =
                *reinterpret_cast<const float4*>(W + (size_t)(k0 + kk) * D + c);
        }
        __syncthreads();
        #pragma unroll
        for (int k = 0; k < 16; ++k) {
            float a[8], b[8];
            #pragma unroll
            for (int i = 0; i < 8; ++i) a[i] = As[k][ty + i * 16];
            #pragma unroll
            for (int j = 0; j < 8; ++j) b[j] = Ws[k][tx + j * 16];
            #pragma unroll
            for (int i = 0; i < 8; ++i)
                #pragma unroll
                for (int j = 0; j < 8; ++j) acc[i][j] = fmaf(a[i], b[j], acc[i][j]);
        }
        __syncthreads();
    }

    float bs[8];
    #pragma unroll
    for (int j = 0; j < 8; ++j) bs[j] = bias[tx + j * 16];
    float psum[8], pssq[8];
    #pragma unroll
    for (int j = 0; j < 8; ++j) { psum[j] = 0.f; pssq[j] = 0.f; }
    #pragma unroll
    for (int i = 0; i < 8; ++i) {
        int grow = rowBase + ty + i * 16;
        if (grow < N_NODES) {
            #pragma unroll
            for (int j = 0; j < 8; ++j) {
                float v = acc[i][j] + bs[j];
                Y[(size_t)grow * D + tx + j * 16] = v;
                psum[j] += v;
                pssq[j] += v * v;
            }
        }
    }
    #pragma unroll
    for (int j = 0; j < 8; ++j) {
        atomicAdd(&g_sum[SOUT][tx + j * 16], psum[j]);
        atomicAdd(&g_ssq[SOUT][tx + j * 16], pssq[j]);
    }
}

// ---------------- finalize column stats -> mean / rstd ------------------------
__global__ void k_finalize(int s) {
    int c = threadIdx.x;
    if (c < D) {
        float m = g_sum[s][c] * (1.0f / N_NODES);
        float var = g_ssq[s][c] * (1.0f / N_NODES) - m * m;
        g_mean[s][c] = m;
        g_rstd[s][c] = rsqrtf(var + BN_EPS);
    }
}

// ---------------- t = relu(bn2(y2)), accumulate stats set 2 -------------------
__global__ __launch_bounds__(256) void k_bnrelu(
    const float* __restrict__ gam, const float* __restrict__ bet)
{
    __shared__ float ssum[D], sssq[D];
    const int tid = threadIdx.x;
    if (tid < D) { ssum[tid] = 0.f; sssq[tid] = 0.f; }
    __syncthreads();

    const int n4 = N_NODES * D / 4;
    const int c4 = (tid & 31) << 2;  // stable column base (stride is mult of 32)
    float m_[4], r_[4], g_[4], b_[4];
    #pragma unroll
    for (int q = 0; q < 4; ++q) {
        m_[q] = g_mean[1][c4 + q];
        r_[q] = g_rstd[1][c4 + q];
        g_[q] = gam[c4 + q];
        b_[q] = bet[c4 + q];
    }
    float lsum[4] = {0.f, 0.f, 0.f, 0.f};
    float lssq[4] = {0.f, 0.f, 0.f, 0.f};
    for (int i = blockIdx.x * blockDim.x + tid; i < n4; i += gridDim.x * blockDim.x) {
        float4 v = reinterpret_cast<const float4*>(g_y2)[i];
        float vv[4] = {v.x, v.y, v.z, v.w};
        #pragma unroll
        for (int q = 0; q < 4; ++q) {
            float t = (vv[q] - m_[q]) * r_[q];
            t = fmaxf(fmaf(g_[q], t, b_[q]), 0.f);
            vv[q] = t;
            lsum[q] += t;
            lssq[q] += t * t;
        }
        reinterpret_cast<float4*>(g_t)[i] = make_float4(vv[0], vv[1], vv[2], vv[3]);
    }
    #pragma unroll
    for (int q = 0; q < 4; ++q) {
        atomicAdd(&ssum[c4 + q], lsum[q]);
        atomicAdd(&sssq[c4 + q], lssq[q]);
    }
    __syncthreads();
    if (tid < D) {
        atomicAdd(&g_sum[2][tid], ssum[tid]);
        atomicAdd(&g_ssq[2][tid], sssq[tid]);
    }
}

// ---------------- out = bn3(t) -----------------------------------------------
__global__ void k_final(const float* __restrict__ gam, const float* __restrict__ bet,
                        float* __restrict__ out)
{
    int i = blockIdx.x * blockDim.x + threadIdx.x;
    const int n4 = N_NODES * D / 4;
    if (i < n4) {
        int c4 = (i & 31) << 2;
        float4 v = reinterpret_cast<const float4*>(g_t)[i];
        float vv[4] = {v.x, v.y, v.z, v.w};
        #pragma unroll
        for (int q = 0; q < 4; ++q) {
            int c = c4 + q;
            float t = (vv[q] - g_mean[2][c]) * g_rstd[2][c];
            vv[q] = fmaf(gam[c], t, bet[c]);
        }
        reinterpret_cast<float4*>(out)[i] = make_float4(vv[0], vv[1], vv[2], vv[3]);
    }
}

// ---------------- launcher ----------------------------------------------------
extern "C" void kernel_launch(void* const* d_in, const int* in_sizes, int n_in,
                              void* d_out, int out_size)
{
    const float* feats = (const float*)d_in[0];
    const int*   src   = (const int*)  d_in[1];
    const int*   dst   = (const int*)  d_in[2];
    const float* W1    = (const float*)d_in[3];
    const float* b1    = (const float*)d_in[4];
    const float* g1    = (const float*)d_in[5];
    const float* be1   = (const float*)d_in[6];
    const float* W2    = (const float*)d_in[7];
    const float* b2    = (const float*)d_in[8];
    const float* g2    = (const float*)d_in[9];
    const float* be2   = (const float*)d_in[10];
    const float* g3    = (const float*)d_in[11];
    const float* be3   = (const float*)d_in[12];
    float* out = (float*)d_out;

    k_zero   <<<(N_NODES + 255) / 256, 256>>>();
    k_count  <<<(N_EDGES + 255) / 256, 256>>>(dst);
    k_scan   <<<1, 1024>>>();
    k_scatter<<<(N_EDGES + 255) / 256, 256>>>(src, dst);
    k_agg    <<<(N_NODES * 32 + 255) / 256, 256>>>(feats);

    k_gemm<0, 0, 0><<<(N_NODES + 127) / 128, 256>>>(W1, b1, g1, be1);
    k_finalize<<<1, 128>>>(0);
    k_gemm<1, 0, 1><<<(N_NODES + 127) / 128, 256>>>(W2, b2, g1, be1);
    k_finalize<<<1, 128>>>(1);
    k_bnrelu<<<592, 256>>>(g2, be2);
    k_finalize<<<1, 128>>>(2);
    k_final<<<(N_NODES * D / 4 + 255) / 256, 256>>>(g3, be3, out);
}